// round 12
// baseline (speedup 1.0000x reference)
#include <cuda_runtime.h>
#include <math.h>

#define N_NODES      100000
#define HIDDEN       256
#define K_CLUSTERS   20
#define CLUSTER_SIZE 5000
#define BLOCKS_PER_CLUSTER 50
#define ROWS_PER_BLOCK (CLUSTER_SIZE / BLOCKS_PER_CLUSTER)   // 100
#define NWARPS 8
#define NGROUPS 4   // pass-1: 4 groups x 64 threads, whole-row float4 reads

// Scratch (allocation-free rule: __device__ globals).
__device__ float g_partial[K_CLUSTERS * BLOCKS_PER_CLUSTER * HIDDEN]; // ~1 MB
__device__ float g_wc[K_CLUSTERS * HIDDEN];

__device__ __forceinline__ float softplus_f(float x) {
    // stable: max(x,0) + log1p(exp(-|x|))
    return fmaxf(x, 0.0f) + log1pf(__expf(-fabsf(x)));
}

__device__ __forceinline__ void add4(float4& a, const float4 v) {
    a.x += v.x; a.y += v.y; a.z += v.z; a.w += v.w;
}

// Pass 1: per-(cluster, block) partial column sums of gathered h1 rows.
// 4 groups of 64 threads; each group reads full 1KB rows via float4 (LDG.128),
// 8 rows batched per iteration -> 128B in flight per thread.
__global__ void __launch_bounds__(HIDDEN)
k_partial_sum(const float* __restrict__ h1, const int* __restrict__ ci) {
    const int k  = blockIdx.y;
    const int b  = blockIdx.x;
    const int t  = threadIdx.x;
    const int g  = t >> 6;          // group 0..3
    const int c4 = t & 63;          // float4 column 0..63
    const int* idx = ci + k * CLUSTER_SIZE + b * ROWS_PER_BLOCK;

    float4 acc = make_float4(0.f, 0.f, 0.f, 0.f);

    int n = g;
    // main loop: 8 rows per iteration (rows n, n+4, ..., n+28 of this group)
    for (; n + 28 < ROWS_PER_BLOCK; n += 8 * NGROUPS) {
        long long r0 = (long long)idx[n];
        long long r1 = (long long)idx[n + 4];
        long long r2 = (long long)idx[n + 8];
        long long r3 = (long long)idx[n + 12];
        long long r4 = (long long)idx[n + 16];
        long long r5 = (long long)idx[n + 20];
        long long r6 = (long long)idx[n + 24];
        long long r7 = (long long)idx[n + 28];
        float4 v0 = reinterpret_cast<const float4*>(h1 + r0 * HIDDEN)[c4];
        float4 v1 = reinterpret_cast<const float4*>(h1 + r1 * HIDDEN)[c4];
        float4 v2 = reinterpret_cast<const float4*>(h1 + r2 * HIDDEN)[c4];
        float4 v3 = reinterpret_cast<const float4*>(h1 + r3 * HIDDEN)[c4];
        float4 v4 = reinterpret_cast<const float4*>(h1 + r4 * HIDDEN)[c4];
        float4 v5 = reinterpret_cast<const float4*>(h1 + r5 * HIDDEN)[c4];
        float4 v6 = reinterpret_cast<const float4*>(h1 + r6 * HIDDEN)[c4];
        float4 v7 = reinterpret_cast<const float4*>(h1 + r7 * HIDDEN)[c4];
        add4(acc, v0); add4(acc, v1); add4(acc, v2); add4(acc, v3);
        add4(acc, v4); add4(acc, v5); add4(acc, v6); add4(acc, v7);
    }
    // remainder
    for (; n < ROWS_PER_BLOCK; n += NGROUPS) {
        long long r = (long long)idx[n];
        add4(acc, reinterpret_cast<const float4*>(h1 + r * HIDDEN)[c4]);
    }

    // combine the 4 groups' column partials via smem
    __shared__ __align__(16) float4 red[NGROUPS][HIDDEN / 4];
    red[g][c4] = acc;
    __syncthreads();

    const float* redf = reinterpret_cast<const float*>(red);
    // redf layout: [g][256] floats
    float s = redf[0 * HIDDEN + t] + redf[1 * HIDDEN + t]
            + redf[2 * HIDDEN + t] + redf[3 * HIDDEN + t];
    g_partial[(k * BLOCKS_PER_CLUSTER + b) * HIDDEN + t] = s;
}

// Pass 2: reduce partials -> mean -> sigmoid -> c; Wc = W @ c. One block per
// cluster. Also zeroes out[0] (poisoned by harness) before pass 3 runs.
__global__ void __launch_bounds__(HIDDEN)
k_make_wc(const float* __restrict__ W, float* __restrict__ out) {
    const int k = blockIdx.x;
    const int d = threadIdx.x;
    __shared__ __align__(16) float c_s[HIDDEN];

    float s = 0.0f;
    #pragma unroll
    for (int b = 0; b < BLOCKS_PER_CLUSTER; ++b)
        s += g_partial[(k * BLOCKS_PER_CLUSTER + b) * HIDDEN + d];

    float m = s * (1.0f / (float)CLUSTER_SIZE);
    c_s[d] = 1.0f / (1.0f + __expf(-m));       // sigmoid
    __syncthreads();

    // Wc[d] = sum_e W[d,e] * c[e]
    const float4* Wr = reinterpret_cast<const float4*>(W + (long long)d * HIDDEN);
    const float4* c4 = reinterpret_cast<const float4*>(c_s);
    float wc = 0.0f;
    #pragma unroll 8
    for (int e = 0; e < HIDDEN / 4; ++e) {
        float4 w4 = Wr[e];
        float4 cc = c4[e];
        wc += w4.x * cc.x + w4.y * cc.y + w4.z * cc.z + w4.w * cc.w;
    }
    g_wc[k * HIDDEN + d] = wc;

    if (k == 0 && d == 0) out[0] = 0.0f;   // runs before k_scores (stream order)
}

// Pass 3: per-row bilinear scores + softplus; warp per row, 2 rows in flight
// per warp iteration for MLP. Each block atomicAdds its pre-scaled sum into out.
__global__ void __launch_bounds__(HIDDEN)
k_scores(const float* __restrict__ h1, const float* __restrict__ h2,
         const int* __restrict__ ci, const float* __restrict__ bptr,
         float* __restrict__ out) {
    const int k    = blockIdx.y;
    const int blk  = blockIdx.x;
    const int tid  = threadIdx.x;
    const int w    = tid >> 5;
    const int lane = tid & 31;

    __shared__ __align__(16) float wc_s[HIDDEN];
    __shared__ float warp_acc[NWARPS];

    wc_s[tid] = g_wc[k * HIDDEN + tid];
    __syncthreads();

    const float bb = *bptr;
    const float4* wc4 = reinterpret_cast<const float4*>(wc_s);
    const float4 wa = wc4[lane];
    const float4 wb = wc4[lane + 32];

    const int* idx = ci + k * CLUSTER_SIZE + blk * ROWS_PER_BLOCK;

    float acc = 0.0f;
    for (int n = w; n < ROWS_PER_BLOCK; n += 2 * NWARPS) {
        const int n2 = n + NWARPS;
        const bool has2 = (n2 < ROWS_PER_BLOCK);

        long long rA = (long long)idx[n];
        long long rB = has2 ? (long long)idx[n2] : rA;

        const float4* p1A = reinterpret_cast<const float4*>(h1 + rA * HIDDEN);
        const float4* p2A = reinterpret_cast<const float4*>(h2 + rA * HIDDEN);
        const float4* p1B = reinterpret_cast<const float4*>(h1 + rB * HIDDEN);
        const float4* p2B = reinterpret_cast<const float4*>(h2 + rB * HIDDEN);

        // Issue all 8 loads before consuming (MLP=8 per thread).
        float4 a0 = p1A[lane], a1 = p1A[lane + 32];
        float4 b0 = p2A[lane], b1 = p2A[lane + 32];
        float4 c0 = p1B[lane], c1 = p1B[lane + 32];
        float4 e0 = p2B[lane], e1 = p2B[lane + 32];

        float s1A = a0.x*wa.x + a0.y*wa.y + a0.z*wa.z + a0.w*wa.w
                  + a1.x*wb.x + a1.y*wb.y + a1.z*wb.z + a1.w*wb.w;
        float s2A = b0.x*wa.x + b0.y*wa.y + b0.z*wa.z + b0.w*wa.w
                  + b1.x*wb.x + b1.y*wb.y + b1.z*wb.z + b1.w*wb.w;
        float s1B = c0.x*wa.x + c0.y*wa.y + c0.z*wa.z + c0.w*wa.w
                  + c1.x*wb.x + c1.y*wb.y + c1.z*wb.z + c1.w*wb.w;
        float s2B = e0.x*wa.x + e0.y*wa.y + e0.z*wa.z + e0.w*wa.w
                  + e1.x*wb.x + e1.y*wb.y + e1.z*wb.z + e1.w*wb.w;

        #pragma unroll
        for (int o = 16; o > 0; o >>= 1) {
            s1A += __shfl_xor_sync(0xFFFFFFFFu, s1A, o);
            s2A += __shfl_xor_sync(0xFFFFFFFFu, s2A, o);
            s1B += __shfl_xor_sync(0xFFFFFFFFu, s1B, o);
            s2B += __shfl_xor_sync(0xFFFFFFFFu, s2B, o);
        }
        acc += softplus_f(-(s1A + bb)) + softplus_f(s2A + bb);
        if (has2)
            acc += softplus_f(-(s1B + bb)) + softplus_f(s2B + bb);
    }

    if (lane == 0) warp_acc[w] = acc;
    __syncthreads();
    if (tid == 0) {
        float t = 0.0f;
        #pragma unroll
        for (int i = 0; i < NWARPS; ++i) t += warp_acc[i];
        // loss contribution, pre-scaled: 0.5 * sum / (K * CLUSTER_SIZE)
        atomicAdd(out, t * (0.5f / (float)(K_CLUSTERS * CLUSTER_SIZE)));
    }
}

extern "C" void kernel_launch(void* const* d_in, const int* in_sizes, int n_in,
                              void* d_out, int out_size) {
    const float* h1 = (const float*)d_in[0];
    const float* h2 = (const float*)d_in[1];
    const int*   ci = (const int*)d_in[2];
    const float* W  = (const float*)d_in[3];
    const float* b  = (const float*)d_in[4];
    float* out = (float*)d_out;

    dim3 grid(BLOCKS_PER_CLUSTER, K_CLUSTERS);
    k_partial_sum<<<grid, HIDDEN>>>(h1, ci);
    k_make_wc<<<K_CLUSTERS, HIDDEN>>>(W, out);
    k_scores<<<grid, HIDDEN>>>(h1, h2, ci, b, out);
}

// round 13
// speedup vs baseline: 1.1593x; 1.1593x over previous
#include <cuda_runtime.h>
#include <math.h>

#define N_NODES      100000
#define HIDDEN       256
#define K_CLUSTERS   20
#define CLUSTER_SIZE 5000

// Pass-1 grid (measured best: occ 81%, 15.5us)
#define P1_BPC  50
#define P1_ROWS (CLUSTER_SIZE / P1_BPC)    // 100
#define NGROUPS 4   // pass-1: 4 groups x 64 threads, whole-row float4 reads

// Scores grid (measured best: 2 waves at ~3 blocks/SM)
#define SC_BPC  40
#define SC_ROWS (CLUSTER_SIZE / SC_BPC)    // 125
#define NWARPS  8

// Scratch (allocation-free rule: __device__ globals).
__device__ float g_partial[K_CLUSTERS * P1_BPC * HIDDEN]; // ~1 MB
__device__ float g_wc[K_CLUSTERS * HIDDEN];

__device__ __forceinline__ float softplus_f(float x) {
    // stable: max(x,0) + log1p(exp(-|x|))
    return fmaxf(x, 0.0f) + log1pf(__expf(-fabsf(x)));
}

__device__ __forceinline__ void add4(float4& a, const float4 v) {
    a.x += v.x; a.y += v.y; a.z += v.z; a.w += v.w;
}

// Pass 1: per-(cluster, block) partial column sums of gathered h1 rows.
// 4 groups of 64 threads; each group reads full 1KB rows via float4 (LDG.128),
// 8 rows batched per iteration -> 128B in flight per thread.
__global__ void __launch_bounds__(HIDDEN)
k_partial_sum(const float* __restrict__ h1, const int* __restrict__ ci) {
    const int k  = blockIdx.y;
    const int b  = blockIdx.x;
    const int t  = threadIdx.x;
    const int g  = t >> 6;          // group 0..3
    const int c4 = t & 63;          // float4 column 0..63
    const int* idx = ci + k * CLUSTER_SIZE + b * P1_ROWS;

    float4 acc = make_float4(0.f, 0.f, 0.f, 0.f);

    int n = g;
    // main loop: 8 rows per iteration (rows n, n+4, ..., n+28 of this group)
    for (; n + 28 < P1_ROWS; n += 8 * NGROUPS) {
        long long r0 = (long long)idx[n];
        long long r1 = (long long)idx[n + 4];
        long long r2 = (long long)idx[n + 8];
        long long r3 = (long long)idx[n + 12];
        long long r4 = (long long)idx[n + 16];
        long long r5 = (long long)idx[n + 20];
        long long r6 = (long long)idx[n + 24];
        long long r7 = (long long)idx[n + 28];
        float4 v0 = reinterpret_cast<const float4*>(h1 + r0 * HIDDEN)[c4];
        float4 v1 = reinterpret_cast<const float4*>(h1 + r1 * HIDDEN)[c4];
        float4 v2 = reinterpret_cast<const float4*>(h1 + r2 * HIDDEN)[c4];
        float4 v3 = reinterpret_cast<const float4*>(h1 + r3 * HIDDEN)[c4];
        float4 v4 = reinterpret_cast<const float4*>(h1 + r4 * HIDDEN)[c4];
        float4 v5 = reinterpret_cast<const float4*>(h1 + r5 * HIDDEN)[c4];
        float4 v6 = reinterpret_cast<const float4*>(h1 + r6 * HIDDEN)[c4];
        float4 v7 = reinterpret_cast<const float4*>(h1 + r7 * HIDDEN)[c4];
        add4(acc, v0); add4(acc, v1); add4(acc, v2); add4(acc, v3);
        add4(acc, v4); add4(acc, v5); add4(acc, v6); add4(acc, v7);
    }
    // remainder
    for (; n < P1_ROWS; n += NGROUPS) {
        long long r = (long long)idx[n];
        add4(acc, reinterpret_cast<const float4*>(h1 + r * HIDDEN)[c4]);
    }

    // combine the 4 groups' column partials via smem
    __shared__ __align__(16) float4 red[NGROUPS][HIDDEN / 4];
    red[g][c4] = acc;
    __syncthreads();

    const float* redf = reinterpret_cast<const float*>(red);
    // redf layout: [g][256] floats
    float s = redf[0 * HIDDEN + t] + redf[1 * HIDDEN + t]
            + redf[2 * HIDDEN + t] + redf[3 * HIDDEN + t];
    g_partial[(k * P1_BPC + b) * HIDDEN + t] = s;
}

// Pass 2: reduce partials -> mean -> sigmoid -> c; Wc = W @ c. One block per
// cluster. Also zeroes out[0] (poisoned by harness) before pass 3 runs.
__global__ void __launch_bounds__(HIDDEN)
k_make_wc(const float* __restrict__ W, float* __restrict__ out) {
    const int k = blockIdx.x;
    const int d = threadIdx.x;
    __shared__ __align__(16) float c_s[HIDDEN];

    float s = 0.0f;
    #pragma unroll
    for (int b = 0; b < P1_BPC; ++b)
        s += g_partial[(k * P1_BPC + b) * HIDDEN + d];

    float m = s * (1.0f / (float)CLUSTER_SIZE);
    c_s[d] = 1.0f / (1.0f + __expf(-m));       // sigmoid
    __syncthreads();

    // Wc[d] = sum_e W[d,e] * c[e]
    const float4* Wr = reinterpret_cast<const float4*>(W + (long long)d * HIDDEN);
    const float4* c4 = reinterpret_cast<const float4*>(c_s);
    float wc = 0.0f;
    #pragma unroll 8
    for (int e = 0; e < HIDDEN / 4; ++e) {
        float4 w4 = Wr[e];
        float4 cc = c4[e];
        wc += w4.x * cc.x + w4.y * cc.y + w4.z * cc.z + w4.w * cc.w;
    }
    g_wc[k * HIDDEN + d] = wc;

    if (k == 0 && d == 0) out[0] = 0.0f;   // runs before k_scores (stream order)
}

// Pass 3: per-row bilinear scores + softplus; warp per row, 2 rows in flight
// per warp iteration for MLP. Each block atomicAdds its pre-scaled sum into out.
__global__ void __launch_bounds__(HIDDEN)
k_scores(const float* __restrict__ h1, const float* __restrict__ h2,
         const int* __restrict__ ci, const float* __restrict__ bptr,
         float* __restrict__ out) {
    const int k    = blockIdx.y;
    const int blk  = blockIdx.x;
    const int tid  = threadIdx.x;
    const int w    = tid >> 5;
    const int lane = tid & 31;

    __shared__ __align__(16) float wc_s[HIDDEN];
    __shared__ float warp_acc[NWARPS];

    wc_s[tid] = g_wc[k * HIDDEN + tid];
    __syncthreads();

    const float bb = *bptr;
    const float4* wc4 = reinterpret_cast<const float4*>(wc_s);
    const float4 wa = wc4[lane];
    const float4 wb = wc4[lane + 32];

    const int* idx = ci + k * CLUSTER_SIZE + blk * SC_ROWS;

    float acc = 0.0f;
    for (int n = w; n < SC_ROWS; n += 2 * NWARPS) {
        const int n2 = n + NWARPS;
        const bool has2 = (n2 < SC_ROWS);

        long long rA = (long long)idx[n];
        long long rB = has2 ? (long long)idx[n2] : rA;

        const float4* p1A = reinterpret_cast<const float4*>(h1 + rA * HIDDEN);
        const float4* p2A = reinterpret_cast<const float4*>(h2 + rA * HIDDEN);
        const float4* p1B = reinterpret_cast<const float4*>(h1 + rB * HIDDEN);
        const float4* p2B = reinterpret_cast<const float4*>(h2 + rB * HIDDEN);

        // Issue all 8 loads before consuming (MLP=8 per thread).
        float4 a0 = p1A[lane], a1 = p1A[lane + 32];
        float4 b0 = p2A[lane], b1 = p2A[lane + 32];
        float4 c0 = p1B[lane], c1 = p1B[lane + 32];
        float4 e0 = p2B[lane], e1 = p2B[lane + 32];

        float s1A = a0.x*wa.x + a0.y*wa.y + a0.z*wa.z + a0.w*wa.w
                  + a1.x*wb.x + a1.y*wb.y + a1.z*wb.z + a1.w*wb.w;
        float s2A = b0.x*wa.x + b0.y*wa.y + b0.z*wa.z + b0.w*wa.w
                  + b1.x*wb.x + b1.y*wb.y + b1.z*wb.z + b1.w*wb.w;
        float s1B = c0.x*wa.x + c0.y*wa.y + c0.z*wa.z + c0.w*wa.w
                  + c1.x*wb.x + c1.y*wb.y + c1.z*wb.z + c1.w*wb.w;
        float s2B = e0.x*wa.x + e0.y*wa.y + e0.z*wa.z + e0.w*wa.w
                  + e1.x*wb.x + e1.y*wb.y + e1.z*wb.z + e1.w*wb.w;

        #pragma unroll
        for (int o = 16; o > 0; o >>= 1) {
            s1A += __shfl_xor_sync(0xFFFFFFFFu, s1A, o);
            s2A += __shfl_xor_sync(0xFFFFFFFFu, s2A, o);
            s1B += __shfl_xor_sync(0xFFFFFFFFu, s1B, o);
            s2B += __shfl_xor_sync(0xFFFFFFFFu, s2B, o);
        }
        acc += softplus_f(-(s1A + bb)) + softplus_f(s2A + bb);
        if (has2)
            acc += softplus_f(-(s1B + bb)) + softplus_f(s2B + bb);
    }

    if (lane == 0) warp_acc[w] = acc;
    __syncthreads();
    if (tid == 0) {
        float t = 0.0f;
        #pragma unroll
        for (int i = 0; i < NWARPS; ++i) t += warp_acc[i];
        // loss contribution, pre-scaled: 0.5 * sum / (K * CLUSTER_SIZE)
        atomicAdd(out, t * (0.5f / (float)(K_CLUSTERS * CLUSTER_SIZE)));
    }
}

extern "C" void kernel_launch(void* const* d_in, const int* in_sizes, int n_in,
                              void* d_out, int out_size) {
    const float* h1 = (const float*)d_in[0];
    const float* h2 = (const float*)d_in[1];
    const int*   ci = (const int*)d_in[2];
    const float* W  = (const float*)d_in[3];
    const float* b  = (const float*)d_in[4];
    float* out = (float*)d_out;

    dim3 grid1(P1_BPC, K_CLUSTERS);
    dim3 grid3(SC_BPC, K_CLUSTERS);
    k_partial_sum<<<grid1, HIDDEN>>>(h1, ci);
    k_make_wc<<<K_CLUSTERS, HIDDEN>>>(W, out);
    k_scores<<<grid3, HIDDEN>>>(h1, h2, ci, b, out);
}